// round 10
// baseline (speedup 1.0000x reference)
#include <cuda_runtime.h>
#include <math.h>

// SPH step — slot counting sort + predicated gather-reduce.
// inputs: r [N,3] f32, v [N,3] f32, i_s [E] i32 (receivers), j_s [E] i32 (senders)
// output: [N,8] f32 = [rho, p, dudt.xyz, 0,0,0]
//
// rho & force: 8 lanes/particle x int4 row load (32 slots/iter, matched to
// mean degree -> full lane utilization, MLP=4 per lane)

#define SIGMA_F 0.0026599711f            /* 3/(359*pi), H=1 */
#define P_REF_F 100.0f
#define EPS_F   1e-8f
#define ETA_IJ_F (2.0f * 0.01f * 0.01f / (0.01f + 0.01f + 1e-8f))

#define MAXN_P 131072          // >= N (N = 100,000)
#define SLOT_SHIFT 7           // 128 slots per particle (Poisson(32) max ~75)
#define SLOT (1 << SLOT_SHIFT)

struct __align__(32) Pk { float4 a; float4 b; };  // a={x,y,z,rho} b={vx,vy,vz,0}

__device__ int g_counts[MAXN_P];
__device__ int g_slots[MAXN_P << SLOT_SHIFT];     // 64 MB, rows always fully allocated
__device__ Pk  g_pack[MAXN_P];

__device__ __forceinline__ float quintic_w(float d) {
    float a = fmaxf(0.0f, 1.0f - d);
    float b = fmaxf(0.0f, 2.0f - d);
    float c = fmaxf(0.0f, 3.0f - d);
    float a5 = a * a; a5 = a5 * a5 * a;
    float b5 = b * b; b5 = b5 * b5 * b;
    float c5 = c * c; c5 = c5 * c5 * c;
    return SIGMA_F * (c5 - 6.0f * b5 + 15.0f * a5);
}

__device__ __forceinline__ float quintic_grad_w(float d) {
    float a = fmaxf(0.0f, 1.0f - d);
    float b = fmaxf(0.0f, 2.0f - d);
    float c = fmaxf(0.0f, 3.0f - d);
    float a4 = a * a; a4 = a4 * a4;
    float b4 = b * b; b4 = b4 * b4;
    float c4 = c * c; c4 = c4 * c4;
    return SIGMA_F * (-5.0f * c4 + 30.0f * b4 - 75.0f * a4);
}

// --------------------------------------------------------------------------
__global__ void pack_zero_kernel(const float* __restrict__ r,
                                 const float* __restrict__ v, int N) {
    int i = blockIdx.x * blockDim.x + threadIdx.x;
    if (i >= N) return;
    float4 a = make_float4(__ldg(&r[3*i]), __ldg(&r[3*i+1]), __ldg(&r[3*i+2]), 0.0f);
    float4 b = make_float4(__ldg(&v[3*i]), __ldg(&v[3*i+1]), __ldg(&v[3*i+2]), 0.0f);
    g_pack[i].a = a;
    g_pack[i].b = b;
    g_counts[i] = 0;
}

// --------------------------------------------------------------------------
// slot-based counting scatter; 4 edges per thread via int4 loads
__global__ void scatter_kernel(const int* __restrict__ i_s,
                               const int* __restrict__ j_s, int E) {
    int t = blockIdx.x * blockDim.x + threadIdx.x;
    int base = t * 4;
    if (base + 3 < E) {
        int4 ii = *(const int4*)(i_s + base);
        int4 jj = *(const int4*)(j_s + base);
        int p;
        p = atomicAdd(&g_counts[ii.x], 1); if (p < SLOT) g_slots[(ii.x << SLOT_SHIFT) + p] = jj.x;
        p = atomicAdd(&g_counts[ii.y], 1); if (p < SLOT) g_slots[(ii.y << SLOT_SHIFT) + p] = jj.y;
        p = atomicAdd(&g_counts[ii.z], 1); if (p < SLOT) g_slots[(ii.z << SLOT_SHIFT) + p] = jj.z;
        p = atomicAdd(&g_counts[ii.w], 1); if (p < SLOT) g_slots[(ii.w << SLOT_SHIFT) + p] = jj.w;
    } else {
        for (int e = base; e < E; e++) {
            int i = i_s[e];
            int p = atomicAdd(&g_counts[i], 1);
            if (p < SLOT) g_slots[(i << SLOT_SHIFT) + p] = j_s[e];
        }
    }
}

// --------------------------------------------------------------------------
// 8 lanes per particle; int4 row load covers 32 slots/iter (mean degree),
// 4 predicated gathers per lane -> MLP=4 with full lane utilization at deg~32.
__global__ void rho_gather_kernel(int N) {
    int tid = blockIdx.x * blockDim.x + threadIdx.x;
    int i = tid >> 3;
    int sl = threadIdx.x & 7;
    if (i >= N) return;
    int deg = g_counts[i];
    if (deg > SLOT) deg = SLOT;
    const int4* row4 = (const int4*)&g_slots[i << SLOT_SHIFT];
    float4 Pi = g_pack[i].a;
    float sum = 0.0f;
    for (int t = 0; t * 32 < deg; t++) {
        int4 jj = row4[t * 8 + sl];           // always in-bounds (row = 128 ints)
        int s0 = t * 32 + 4 * sl;
        #pragma unroll
        for (int u = 0; u < 4; u++) {
            int j = (u == 0) ? jj.x : (u == 1) ? jj.y : (u == 2) ? jj.z : jj.w;
            if (s0 + u < deg) {
                float4 Pj = g_pack[j].a;
                float dx = Pi.x - Pj.x, dy = Pi.y - Pj.y, dz = Pi.z - Pj.z;
                sum += quintic_w(sqrtf(dx*dx + dy*dy + dz*dz));
            }
        }
    }
    #pragma unroll
    for (int o = 4; o; o >>= 1) sum += __shfl_xor_sync(~0u, sum, o);
    if (sl == 0) g_pack[i].a.w = sum;
}

// --------------------------------------------------------------------------
// 8 lanes per particle; int4 row load (32 slots/iter), predicated gathers;
// writes all 8 output columns via two float4 stores.
__global__ void force_gather_kernel(float* __restrict__ out, int N) {
    int tid = blockIdx.x * blockDim.x + threadIdx.x;
    int i = tid >> 3;
    int sl = threadIdx.x & 7;
    if (i >= N) return;
    int deg = g_counts[i];
    if (deg > SLOT) deg = SLOT;
    const int4* row4 = (const int4*)&g_slots[i << SLOT_SHIFT];
    float4 Pa_i = g_pack[i].a;
    float4 Pb_i = g_pack[i].b;
    float rho_i = Pa_i.w;
    float inv_i = __fdividef(1.0f, rho_i);
    float inv_i2 = inv_i * inv_i;

    float ax = 0.0f, ay = 0.0f, az = 0.0f;
    for (int t = 0; t * 32 < deg; t++) {
        int4 jj = row4[t * 8 + sl];
        int s0 = t * 32 + 4 * sl;
        #pragma unroll
        for (int u = 0; u < 4; u++) {
            int j = (u == 0) ? jj.x : (u == 1) ? jj.y : (u == 2) ? jj.z : jj.w;
            if (s0 + u < deg) {
                float4 Pa_j = g_pack[j].a;
                float4 Pb_j = g_pack[j].b;
                float dx = Pa_i.x - Pa_j.x, dy = Pa_i.y - Pa_j.y, dz = Pa_i.z - Pa_j.z;
                float d = sqrtf(dx*dx + dy*dy + dz*dz);
                float rho_j = Pa_j.w;
                // p_ij = (rho_j*p_i + rho_i*p_j)/(rho_i+rho_j) = 100*(2 rho_i rho_j/s - 1)
                float inv_s = __fdividef(1.0f, rho_i + rho_j);
                float p_ij = P_REF_F * (2.0f * rho_i * rho_j * inv_s - 1.0f);
                float inv_j = __fdividef(1.0f, rho_j);
                float wvol = inv_i2 + inv_j * inv_j;
                float c = wvol * quintic_grad_w(d) * __fdividef(1.0f, d + EPS_F);
                float dvx = Pb_i.x - Pb_j.x, dvy = Pb_i.y - Pb_j.y, dvz = Pb_i.z - Pb_j.z;
                ax += c * (-p_ij * dx + ETA_IJ_F * dvx);
                ay += c * (-p_ij * dy + ETA_IJ_F * dvy);
                az += c * (-p_ij * dz + ETA_IJ_F * dvz);
            }
        }
    }
    #pragma unroll
    for (int o = 4; o; o >>= 1) {
        ax += __shfl_xor_sync(~0u, ax, o);
        ay += __shfl_xor_sync(~0u, ay, o);
        az += __shfl_xor_sync(~0u, az, o);
    }
    if (sl == 0) {
        float4* o4 = (float4*)(out + 8 * i);
        o4[0] = make_float4(rho_i, P_REF_F * (rho_i - 1.0f), ax, ay);
        o4[1] = make_float4(az, 0.0f, 0.0f, 0.0f);
    }
}

// --------------------------------------------------------------------------
extern "C" void kernel_launch(void* const* d_in, const int* in_sizes, int n_in,
                              void* d_out, int out_size) {
    const float* r   = (const float*)d_in[0];
    const float* v   = (const float*)d_in[1];
    const int*   i_s = (const int*)d_in[2];
    const int*   j_s = (const int*)d_in[3];
    float* out = (float*)d_out;

    int N = in_sizes[0] / 3;
    int E = in_sizes[2];

    const int TB = 256;
    pack_zero_kernel<<<(N + TB - 1) / TB, TB>>>(r, v, N);
    int nthreads = (E + 3) / 4;
    scatter_kernel<<<(nthreads + TB - 1) / TB, TB>>>(i_s, j_s, E);
    // 8 lanes/particle -> 32 particles per 256-thread block
    rho_gather_kernel<<<(N + 31) / 32, TB>>>(N);
    force_gather_kernel<<<(N + 31) / 32, TB>>>(out, N);
}

// round 11
// speedup vs baseline: 1.0195x; 1.0195x over previous
#include <cuda_runtime.h>
#include <math.h>

// SPH step — slot counting sort + predicated gather-reduce. 3 kernels:
//   1. scatter_pack : counting-scatter edges into slots; first N threads also
//                     pack particle fields into one 32B sector each.
//                     (g_counts starts zero: zero-initialized at module load,
//                      and restored to zero by force_gather each call.)
//   2. rho_gather   : 8 lanes/particle, int4 row, predicated pack gathers.
//   3. force_gather : 8 lanes/particle, writes out[N,8]; epilogue re-zeroes counts.

#define SIGMA_F 0.0026599711f            /* 3/(359*pi), H=1 */
#define P_REF_F 100.0f
#define EPS_F   1e-8f
#define ETA_IJ_F (2.0f * 0.01f * 0.01f / (0.01f + 0.01f + 1e-8f))

#define MAXN_P 131072          // >= N (N = 100,000)
#define SLOT_SHIFT 7           // 128 slots per particle (Poisson(32) max ~75)
#define SLOT (1 << SLOT_SHIFT)

struct __align__(32) Pk { float4 a; float4 b; };  // a={x,y,z,rho} b={vx,vy,vz,0}

__device__ int g_counts[MAXN_P];                  // zero-init at load; restored by force
__device__ int g_slots[MAXN_P << SLOT_SHIFT];     // 64 MB, rows always fully allocated
__device__ Pk  g_pack[MAXN_P];

__device__ __forceinline__ float quintic_w(float d) {
    float a = fmaxf(0.0f, 1.0f - d);
    float b = fmaxf(0.0f, 2.0f - d);
    float c = fmaxf(0.0f, 3.0f - d);
    float a5 = a * a; a5 = a5 * a5 * a;
    float b5 = b * b; b5 = b5 * b5 * b;
    float c5 = c * c; c5 = c5 * c5 * c;
    return SIGMA_F * (c5 - 6.0f * b5 + 15.0f * a5);
}

__device__ __forceinline__ float quintic_grad_w(float d) {
    float a = fmaxf(0.0f, 1.0f - d);
    float b = fmaxf(0.0f, 2.0f - d);
    float c = fmaxf(0.0f, 3.0f - d);
    float a4 = a * a; a4 = a4 * a4;
    float b4 = b * b; b4 = b4 * b4;
    float c4 = c * c; c4 = c4 * c4;
    return SIGMA_F * (-5.0f * c4 + 30.0f * b4 - 75.0f * a4);
}

// --------------------------------------------------------------------------
// Combined: counting-scatter (4 edges/thread) + particle packing (tid < N).
__global__ void scatter_pack_kernel(const float* __restrict__ r,
                                    const float* __restrict__ v,
                                    const int* __restrict__ i_s,
                                    const int* __restrict__ j_s,
                                    int N, int E) {
    int t = blockIdx.x * blockDim.x + threadIdx.x;

    // pack (independent of scatter writes)
    if (t < N) {
        float4 a = make_float4(__ldg(&r[3*t]), __ldg(&r[3*t+1]), __ldg(&r[3*t+2]), 0.0f);
        float4 b = make_float4(__ldg(&v[3*t]), __ldg(&v[3*t+1]), __ldg(&v[3*t+2]), 0.0f);
        g_pack[t].a = a;
        g_pack[t].b = b;
    }

    // scatter
    int base = t * 4;
    if (base + 3 < E) {
        int4 ii = *(const int4*)(i_s + base);
        int4 jj = *(const int4*)(j_s + base);
        int p;
        p = atomicAdd(&g_counts[ii.x], 1); if (p < SLOT) g_slots[(ii.x << SLOT_SHIFT) + p] = jj.x;
        p = atomicAdd(&g_counts[ii.y], 1); if (p < SLOT) g_slots[(ii.y << SLOT_SHIFT) + p] = jj.y;
        p = atomicAdd(&g_counts[ii.z], 1); if (p < SLOT) g_slots[(ii.z << SLOT_SHIFT) + p] = jj.z;
        p = atomicAdd(&g_counts[ii.w], 1); if (p < SLOT) g_slots[(ii.w << SLOT_SHIFT) + p] = jj.w;
    } else if (base < E) {
        for (int e = base; e < E; e++) {
            int i = i_s[e];
            int p = atomicAdd(&g_counts[i], 1);
            if (p < SLOT) g_slots[(i << SLOT_SHIFT) + p] = j_s[e];
        }
    }
}

// --------------------------------------------------------------------------
// 8 lanes per particle; int4 row load covers 32 slots/iter (mean degree),
// 4 predicated gathers per lane -> MLP=4 with full lane utilization at deg~32.
__global__ void rho_gather_kernel(int N) {
    int tid = blockIdx.x * blockDim.x + threadIdx.x;
    int i = tid >> 3;
    int sl = threadIdx.x & 7;
    if (i >= N) return;
    int deg = g_counts[i];
    if (deg > SLOT) deg = SLOT;
    const int4* row4 = (const int4*)&g_slots[i << SLOT_SHIFT];
    float4 Pi = g_pack[i].a;
    float sum = 0.0f;
    for (int t = 0; t * 32 < deg; t++) {
        int4 jj = row4[t * 8 + sl];           // always in-bounds (row = 128 ints)
        int s0 = t * 32 + 4 * sl;
        #pragma unroll
        for (int u = 0; u < 4; u++) {
            int j = (u == 0) ? jj.x : (u == 1) ? jj.y : (u == 2) ? jj.z : jj.w;
            if (s0 + u < deg) {
                float4 Pj = g_pack[j].a;
                float dx = Pi.x - Pj.x, dy = Pi.y - Pj.y, dz = Pi.z - Pj.z;
                sum += quintic_w(sqrtf(dx*dx + dy*dy + dz*dz));
            }
        }
    }
    #pragma unroll
    for (int o = 4; o; o >>= 1) sum += __shfl_xor_sync(~0u, sum, o);
    if (sl == 0) g_pack[i].a.w = sum;
}

// --------------------------------------------------------------------------
// 8 lanes per particle; writes all 8 output columns via two float4 stores.
// Epilogue restores g_counts[i] = 0 for the next kernel_launch call
// (safe: the shfl reduction converges the warp, so all lanes' deg reads
//  happen-before the store; only this group touches particle i).
__global__ void force_gather_kernel(float* __restrict__ out, int N) {
    int tid = blockIdx.x * blockDim.x + threadIdx.x;
    int i = tid >> 3;
    int sl = threadIdx.x & 7;
    if (i >= N) return;
    int deg = g_counts[i];
    if (deg > SLOT) deg = SLOT;
    const int4* row4 = (const int4*)&g_slots[i << SLOT_SHIFT];
    float4 Pa_i = g_pack[i].a;
    float4 Pb_i = g_pack[i].b;
    float rho_i = Pa_i.w;
    float inv_i = __fdividef(1.0f, rho_i);
    float inv_i2 = inv_i * inv_i;

    float ax = 0.0f, ay = 0.0f, az = 0.0f;
    for (int t = 0; t * 32 < deg; t++) {
        int4 jj = row4[t * 8 + sl];
        int s0 = t * 32 + 4 * sl;
        #pragma unroll
        for (int u = 0; u < 4; u++) {
            int j = (u == 0) ? jj.x : (u == 1) ? jj.y : (u == 2) ? jj.z : jj.w;
            if (s0 + u < deg) {
                float4 Pa_j = g_pack[j].a;
                float4 Pb_j = g_pack[j].b;
                float dx = Pa_i.x - Pa_j.x, dy = Pa_i.y - Pa_j.y, dz = Pa_i.z - Pa_j.z;
                float d = sqrtf(dx*dx + dy*dy + dz*dz);
                float rho_j = Pa_j.w;
                // p_ij = (rho_j*p_i + rho_i*p_j)/(rho_i+rho_j) = 100*(2 rho_i rho_j/s - 1)
                float inv_s = __fdividef(1.0f, rho_i + rho_j);
                float p_ij = P_REF_F * (2.0f * rho_i * rho_j * inv_s - 1.0f);
                float inv_j = __fdividef(1.0f, rho_j);
                float wvol = inv_i2 + inv_j * inv_j;
                float c = wvol * quintic_grad_w(d) * __fdividef(1.0f, d + EPS_F);
                float dvx = Pb_i.x - Pb_j.x, dvy = Pb_i.y - Pb_j.y, dvz = Pb_i.z - Pb_j.z;
                ax += c * (-p_ij * dx + ETA_IJ_F * dvx);
                ay += c * (-p_ij * dy + ETA_IJ_F * dvy);
                az += c * (-p_ij * dz + ETA_IJ_F * dvz);
            }
        }
    }
    #pragma unroll
    for (int o = 4; o; o >>= 1) {
        ax += __shfl_xor_sync(~0u, ax, o);
        ay += __shfl_xor_sync(~0u, ay, o);
        az += __shfl_xor_sync(~0u, az, o);
    }
    if (sl == 0) {
        float4* o4 = (float4*)(out + 8 * i);
        o4[0] = make_float4(rho_i, P_REF_F * (rho_i - 1.0f), ax, ay);
        o4[1] = make_float4(az, 0.0f, 0.0f, 0.0f);
        g_counts[i] = 0;      // restore invariant for the next call
    }
}

// --------------------------------------------------------------------------
extern "C" void kernel_launch(void* const* d_in, const int* in_sizes, int n_in,
                              void* d_out, int out_size) {
    const float* r   = (const float*)d_in[0];
    const float* v   = (const float*)d_in[1];
    const int*   i_s = (const int*)d_in[2];
    const int*   j_s = (const int*)d_in[3];
    float* out = (float*)d_out;

    int N = in_sizes[0] / 3;
    int E = in_sizes[2];

    const int TB = 256;
    int nthreads = (E + 3) / 4;          // >= N for this problem (800k vs 100k)
    if (nthreads < N) nthreads = N;
    scatter_pack_kernel<<<(nthreads + TB - 1) / TB, TB>>>(r, v, i_s, j_s, N, E);
    // 8 lanes/particle -> 32 particles per 256-thread block
    rho_gather_kernel<<<(N + 31) / 32, TB>>>(N);
    force_gather_kernel<<<(N + 31) / 32, TB>>>(out, N);
}

// round 13
// speedup vs baseline: 1.0802x; 1.0595x over previous
#include <cuda_runtime.h>
#include <math.h>

// SPH step — two-level smem-radix counting sort + predicated gather-reduce.
// inputs: r [N,3] f32, v [N,3] f32, i_s [E] i32 (receivers), j_s [E] i32 (senders)
// output: [N,8] f32 = [rho, p, dudt.xyz, 0,0,0]
//
// Pipeline (4 kernels):
//   1. p1_bin_pack : partition edges into buckets of 512 receivers via smem
//                    staging (coalesced global writes); folds particle packing.
//   2. p2_build    : per bucket, coalesced read of packed edges, smem row
//                    binning, coalesced int4 row writes to g_slots + counts.
//                    Re-zeroes its bucket cursor (replay-safe).
//   3. rho_gather  : 8 lanes/particle, int4 row, predicated pack gathers.
//   4. force_gather: 8 lanes/particle, writes out[N,8].
//
// Capacity math (N=100k, E=3.2M): 196 ACTIVE buckets (i<100k), mean
// 16,384 edges/bucket (sigma 128) -> CAPB=18432 (+16 sigma). Per-tile bucket
// mean 20.9 (sigma 4.6) -> P1_CAP=48 (+6 sigma, plus direct-global fallback).
// Row degree Poisson(32) -> ROWCAP=88 (+10 sigma).

#define SIGMA_F 0.0026599711f            /* 3/(359*pi), H=1 */
#define P_REF_F 100.0f
#define EPS_F   1e-8f
#define ETA_IJ_F (2.0f * 0.01f * 0.01f / (0.01f + 0.01f + 1e-8f))

#define MAXN_P 131072          // >= N (N = 100,000); j must fit 17 bits
#define SLOT_SHIFT 7           // 128 slots per particle row in g_slots
#define SLOT (1 << SLOT_SHIFT)

#define NB      256            // bucket slots (196 active)
#define RPB_SH  9
#define RPB     (1 << RPB_SH)  // 512 receivers per bucket
#define CAPB    18432          // bin capacity per bucket (mean 16384, +16 sigma)
#define P1_TILE 4096           // edges per pass-1 tile
#define P1_CAP  48             // smem staging entries per bucket per tile
#define ROWCAP  88             // pass-2 smem slots per receiver (+10 sigma)
#define P2_THREADS 512
#define P2_SMEM ((RPB + RPB * ROWCAP) * 4)   // 182,272 B dynamic

struct __align__(32) Pk { float4 a; float4 b; };  // a={x,y,z,rho} b={vx,vy,vz,0}

__device__ int g_bcursor[NB];                     // zero-init; reset by p2 each call
__device__ int g_bins[NB * CAPB];                 // packed (i_low<<17 | j)
__device__ int g_counts[MAXN_P];                  // overwritten by p2 each call
__device__ int g_slots[MAXN_P << SLOT_SHIFT];     // 64 MB
__device__ Pk  g_pack[MAXN_P];

__device__ __forceinline__ float quintic_w(float d) {
    float a = fmaxf(0.0f, 1.0f - d);
    float b = fmaxf(0.0f, 2.0f - d);
    float c = fmaxf(0.0f, 3.0f - d);
    float a5 = a * a; a5 = a5 * a5 * a;
    float b5 = b * b; b5 = b5 * b5 * b;
    float c5 = c * c; c5 = c5 * c5 * c;
    return SIGMA_F * (c5 - 6.0f * b5 + 15.0f * a5);
}

__device__ __forceinline__ float quintic_grad_w(float d) {
    float a = fmaxf(0.0f, 1.0f - d);
    float b = fmaxf(0.0f, 2.0f - d);
    float c = fmaxf(0.0f, 3.0f - d);
    float a4 = a * a; a4 = a4 * a4;
    float b4 = b * b; b4 = b4 * b4;
    float c4 = c * c; c4 = c4 * c4;
    return SIGMA_F * (-5.0f * c4 + 30.0f * b4 - 75.0f * a4);
}

// --------------------------------------------------------------------------
__device__ __forceinline__ void p1_push(int i, int j, int* scnt, int* sbuf) {
    int b = i >> RPB_SH;
    int val = ((i & (RPB - 1)) << 17) | j;
    int p = atomicAdd(&scnt[b], 1);
    if (p < P1_CAP) {
        sbuf[b * P1_CAP + p] = val;
    } else {                                  // rare overflow: direct global
        int g = atomicAdd(&g_bcursor[b], 1);
        if (g < CAPB) g_bins[b * CAPB + g] = val;
    }
}

// Pass 1: bucket-partition edges with smem staging; fold particle packing.
__global__ void p1_bin_pack_kernel(const float* __restrict__ r,
                                   const float* __restrict__ v,
                                   const int* __restrict__ i_s,
                                   const int* __restrict__ j_s,
                                   int N, int E) {
    __shared__ int sbuf[NB * P1_CAP];
    __shared__ int scnt[NB];
    __shared__ int sbase[NB];
    int tid = threadIdx.x;
    int gtid = blockIdx.x * blockDim.x + tid;

    if (gtid < N) {
        float4 a = make_float4(__ldg(&r[3*gtid]), __ldg(&r[3*gtid+1]), __ldg(&r[3*gtid+2]), 0.0f);
        float4 b = make_float4(__ldg(&v[3*gtid]), __ldg(&v[3*gtid+1]), __ldg(&v[3*gtid+2]), 0.0f);
        g_pack[gtid].a = a;
        g_pack[gtid].b = b;
    }

    int ntiles = (E + P1_TILE - 1) / P1_TILE;
    for (int tile = blockIdx.x; tile < ntiles; tile += gridDim.x) {
        if (tid < NB) scnt[tid] = 0;
        __syncthreads();

        int base = tile * P1_TILE + tid * 16;
        if (base + 15 < E) {
            #pragma unroll
            for (int q = 0; q < 4; q++) {
                int4 ii = *(const int4*)(i_s + base + q * 4);
                int4 jj = *(const int4*)(j_s + base + q * 4);
                p1_push(ii.x, jj.x, scnt, sbuf);
                p1_push(ii.y, jj.y, scnt, sbuf);
                p1_push(ii.z, jj.z, scnt, sbuf);
                p1_push(ii.w, jj.w, scnt, sbuf);
            }
        } else {
            for (int e = base; e < E && e < base + 16; e++)
                p1_push(i_s[e], j_s[e], scnt, sbuf);
        }
        __syncthreads();

        if (tid < NB) {
            int c = scnt[tid];
            if (c > P1_CAP) c = P1_CAP;
            scnt[tid] = c;
            sbase[tid] = (c > 0) ? atomicAdd(&g_bcursor[tid], c) : 0;
        }
        __syncthreads();

        // warp-per-bucket flush: lanes write contiguous entries (coalesced bursts)
        int wid = tid >> 5, lane = tid & 31;
        for (int b = wid; b < NB; b += 8) {
            int c = scnt[b];
            int gb = sbase[b];
            for (int k = lane; k < c; k += 32) {
                if (gb + k < CAPB) g_bins[b * CAPB + gb + k] = sbuf[b * P1_CAP + k];
            }
        }
        __syncthreads();
    }
}

// --------------------------------------------------------------------------
// Pass 2: per bucket, smem row binning + coalesced row/count output.
__global__ void p2_build_kernel(int N) {
    extern __shared__ int sm[];
    int* scnt = sm;                 // [RPB]
    int* srow = sm + RPB;           // [RPB * ROWCAP]
    int b = blockIdx.x;
    int tid = threadIdx.x;          // P2_THREADS == RPB == 512

    scnt[tid] = 0;
    int nb = g_bcursor[b];
    if (nb > CAPB) nb = CAPB;
    __syncthreads();

    for (int k = tid; k < nb; k += P2_THREADS) {
        int val = g_bins[b * CAPB + k];
        int il = val >> 17;                       // 0..511
        int j  = val & 0x1FFFF;
        int p = atomicAdd(&scnt[il], 1);
        if (p < ROWCAP) srow[il * ROWCAP + p] = j;
    }
    __syncthreads();

    // counts + cursor reset (all reads of cursor happened before this sync)
    {
        int i = b * RPB + tid;
        int d = scnt[tid];
        if (d > ROWCAP) d = ROWCAP;
        if (i < N) { g_counts[i] = d; scnt[tid] = d; }
        else scnt[tid] = 0;
        if (tid == 0) g_bcursor[b] = 0;
    }
    __syncthreads();

    // copy rows out as int4 chunks (coalesced within/between adjacent rows)
    const int CH = ROWCAP / 4;      // 22 chunks per row
    for (int idx = tid; idx < RPB * CH; idx += P2_THREADS) {
        int rrow = idx / CH;
        int c = idx - rrow * CH;
        if (c * 4 < scnt[rrow]) {
            int i = b * RPB + rrow;   // i < N guaranteed (scnt 0 otherwise)
            int4 vv = *(int4*)&srow[rrow * ROWCAP + c * 4];
            *(int4*)&g_slots[(i << SLOT_SHIFT) + c * 4] = vv;
        }
    }
}

// --------------------------------------------------------------------------
// 8 lanes per particle; int4 row load covers 32 slots/iter (mean degree),
// 4 predicated gathers per lane -> MLP=4 with full lane utilization at deg~32.
__global__ void rho_gather_kernel(int N) {
    int tid = blockIdx.x * blockDim.x + threadIdx.x;
    int i = tid >> 3;
    int sl = threadIdx.x & 7;
    if (i >= N) return;
    int deg = g_counts[i];
    if (deg > SLOT) deg = SLOT;
    const int4* row4 = (const int4*)&g_slots[i << SLOT_SHIFT];
    float4 Pi = g_pack[i].a;
    float sum = 0.0f;
    for (int t = 0; t * 32 < deg; t++) {
        int4 jj = row4[t * 8 + sl];
        int s0 = t * 32 + 4 * sl;
        #pragma unroll
        for (int u = 0; u < 4; u++) {
            int j = (u == 0) ? jj.x : (u == 1) ? jj.y : (u == 2) ? jj.z : jj.w;
            if (s0 + u < deg) {
                float4 Pj = g_pack[j].a;
                float dx = Pi.x - Pj.x, dy = Pi.y - Pj.y, dz = Pi.z - Pj.z;
                sum += quintic_w(sqrtf(dx*dx + dy*dy + dz*dz));
            }
        }
    }
    #pragma unroll
    for (int o = 4; o; o >>= 1) sum += __shfl_xor_sync(~0u, sum, o);
    if (sl == 0) g_pack[i].a.w = sum;
}

// --------------------------------------------------------------------------
// 8 lanes per particle; writes all 8 output columns via two float4 stores.
__global__ void force_gather_kernel(float* __restrict__ out, int N) {
    int tid = blockIdx.x * blockDim.x + threadIdx.x;
    int i = tid >> 3;
    int sl = threadIdx.x & 7;
    if (i >= N) return;
    int deg = g_counts[i];
    if (deg > SLOT) deg = SLOT;
    const int4* row4 = (const int4*)&g_slots[i << SLOT_SHIFT];
    float4 Pa_i = g_pack[i].a;
    float4 Pb_i = g_pack[i].b;
    float rho_i = Pa_i.w;
    float inv_i = __fdividef(1.0f, rho_i);
    float inv_i2 = inv_i * inv_i;

    float ax = 0.0f, ay = 0.0f, az = 0.0f;
    for (int t = 0; t * 32 < deg; t++) {
        int4 jj = row4[t * 8 + sl];
        int s0 = t * 32 + 4 * sl;
        #pragma unroll
        for (int u = 0; u < 4; u++) {
            int j = (u == 0) ? jj.x : (u == 1) ? jj.y : (u == 2) ? jj.z : jj.w;
            if (s0 + u < deg) {
                float4 Pa_j = g_pack[j].a;
                float4 Pb_j = g_pack[j].b;
                float dx = Pa_i.x - Pa_j.x, dy = Pa_i.y - Pa_j.y, dz = Pa_i.z - Pa_j.z;
                float d = sqrtf(dx*dx + dy*dy + dz*dz);
                float rho_j = Pa_j.w;
                // p_ij = (rho_j*p_i + rho_i*p_j)/(rho_i+rho_j) = 100*(2 rho_i rho_j/s - 1)
                float inv_s = __fdividef(1.0f, rho_i + rho_j);
                float p_ij = P_REF_F * (2.0f * rho_i * rho_j * inv_s - 1.0f);
                float inv_j = __fdividef(1.0f, rho_j);
                float wvol = inv_i2 + inv_j * inv_j;
                float c = wvol * quintic_grad_w(d) * __fdividef(1.0f, d + EPS_F);
                float dvx = Pb_i.x - Pb_j.x, dvy = Pb_i.y - Pb_j.y, dvz = Pb_i.z - Pb_j.z;
                ax += c * (-p_ij * dx + ETA_IJ_F * dvx);
                ay += c * (-p_ij * dy + ETA_IJ_F * dvy);
                az += c * (-p_ij * dz + ETA_IJ_F * dvz);
            }
        }
    }
    #pragma unroll
    for (int o = 4; o; o >>= 1) {
        ax += __shfl_xor_sync(~0u, ax, o);
        ay += __shfl_xor_sync(~0u, ay, o);
        az += __shfl_xor_sync(~0u, az, o);
    }
    if (sl == 0) {
        float4* o4 = (float4*)(out + 8 * i);
        o4[0] = make_float4(rho_i, P_REF_F * (rho_i - 1.0f), ax, ay);
        o4[1] = make_float4(az, 0.0f, 0.0f, 0.0f);
    }
}

// --------------------------------------------------------------------------
extern "C" void kernel_launch(void* const* d_in, const int* in_sizes, int n_in,
                              void* d_out, int out_size) {
    const float* r   = (const float*)d_in[0];
    const float* v   = (const float*)d_in[1];
    const int*   i_s = (const int*)d_in[2];
    const int*   j_s = (const int*)d_in[3];
    float* out = (float*)d_out;

    int N = in_sizes[0] / 3;
    int E = in_sizes[2];

    // idempotent; needed for pass-2's 182KB dynamic smem (not a stream op)
    cudaFuncSetAttribute(p2_build_kernel,
                         cudaFuncAttributeMaxDynamicSharedMemorySize, P2_SMEM);

    p1_bin_pack_kernel<<<592, 256>>>(r, v, i_s, j_s, N, E);
    int nbuckets = (N + RPB - 1) / RPB;
    p2_build_kernel<<<nbuckets, P2_THREADS, P2_SMEM>>>(N);
    // 8 lanes/particle -> 32 particles per 256-thread block
    rho_gather_kernel<<<(N + 31) / 32, 256>>>(N);
    force_gather_kernel<<<(N + 31) / 32, 256>>>(out, N);
}